// round 16
// baseline (speedup 1.0000x reference)
#include <cuda_runtime.h>
#include <cstdint>

#define C_DIM 256
#define N_TOK 8
#define D_DIM 512
#define HW    4096
#define B_SZ  4
#define EPS   1e-6f
#define N_TILES 512

// ---- persistent scratch ----
__device__ float g_sgp[16][B_SZ * C_DIM];
__device__ float g_wovp[16][C_DIM * C_DIM];   // partials (4MB), non-atomic
__device__ float g_wovgT[C_DIM * C_DIM];      // [ch][co]
__device__ int   g_tile_ctr;                  // dynamic tile counter

#define FMA2(d, a, b, c) \
    asm("fma.rn.f32x2 %0, %1, %2, %3;" : "=l"(d) : "l"(a), "l"(b), "l"(c))
#define DUP2(d, x) \
    asm("mov.b64 %0, {%1, %1};" : "=l"(d) : "r"(__float_as_uint(x)))

// ---------------------------------------------------------------------------
// L0 k_pro: merged prologue, 320 blocks.
//   [0,256):  wov partials, 16 co x 32 d per block (8MB Wv traffic, was 32MB)
//   [256,320): sg partials
// ---------------------------------------------------------------------------
__global__ void k_pro(const float* __restrict__ q,  const float* __restrict__ Wq,
                      const float* __restrict__ Wkv, const float* __restrict__ Wo) {
    int blk = blockIdx.x, tid = threadIdx.x;
    if (blk < 256) {
        int co0 = (blk >> 4) * 16, kc = blk & 15;
        __shared__ float wo_s[16][32];
        #pragma unroll
        for (int k = 0; k < 2; ++k) {
            int idx = tid + k * 256;
            int r = idx >> 5, cc = idx & 31;
            wo_s[r][cc] = __ldg(&Wo[(co0 + r) * D_DIM + kc * 32 + cc]);
        }
        __syncthreads();
        const float* wv = Wkv + (size_t)(D_DIM + kc * 32) * C_DIM + tid;
        float a[16];
        #pragma unroll
        for (int r = 0; r < 16; ++r) a[r] = 0.f;
        #pragma unroll 4
        for (int d = 0; d < 32; ++d) {
            float v = __ldg(wv + (size_t)d * C_DIM);
            #pragma unroll
            for (int r = 0; r < 16; ++r) a[r] += wo_s[r][d] * v;
        }
        float* o = &g_wovp[kc][tid * C_DIM + co0];
        #pragma unroll
        for (int r = 0; r < 16; ++r) o[r] = a[r];
    } else {
        int s = blk - 256;
        int b = s >> 4, ck = s & 15;
        __shared__ float qs[C_DIM];
        __shared__ float qps[32];
        qs[tid] = q[b * C_DIM + tid];
        __syncthreads();
        {
            int dl = tid >> 3, sl = tid & 7;
            const float* wq = Wq + (size_t)(ck * 32 + dl) * C_DIM + sl * 32;
            float a = 0.f;
            #pragma unroll
            for (int k = 0; k < 32; ++k) a += __ldg(wq + k) * qs[sl * 32 + k];
            a += __shfl_xor_sync(0xffffffffu, a, 1);
            a += __shfl_xor_sync(0xffffffffu, a, 2);
            a += __shfl_xor_sync(0xffffffffu, a, 4);
            if (sl == 0) qps[dl] = a;
        }
        __syncthreads();
        float a = 0.f;
        const float* wk = Wkv + (size_t)(ck * 32) * C_DIM + tid;
        #pragma unroll
        for (int d = 0; d < 32; ++d) a += __ldg(wk + (size_t)d * C_DIM) * qps[d];
        g_sgp[ck][b * C_DIM + tid] = a;
    }
}

// ---------------------------------------------------------------------------
// L1/L2 k_wovr: reduce partials; first one resets the tile counter.
// ---------------------------------------------------------------------------
__global__ void k_wovr(const float* __restrict__ g, int base) {
    if (base == 0 && blockIdx.x == 0 && threadIdx.x == 0) g_tile_ctr = 0;
    int idx = base + blockIdx.x * 256 + threadIdx.x;
    float s = 0.f;
    #pragma unroll
    for (int i = 0; i < 16; ++i) s += g_wovp[i][idx];
    g_wovgT[idx] = s * g[idx >> 8];
}

// ---------------------------------------------------------------------------
// L3 k_main v6: persistent + dynamic tiles (R15) + 16-ch chunks so the
// double-buffered weight pipeline fits 3 blocks/SM (37KB dyn smem).
// ---------------------------------------------------------------------------
#define KCH 16
#define AGG_STRIDE 36
#define MAIN_SMEM (2 * KCH * AGG_STRIDE * 4 + 2 * KCH * C_DIM * 4)   // 37376B
__global__ void __launch_bounds__(256, 3) k_main(const float* __restrict__ c,
                                                 const float* __restrict__ g,
                                                 const float* __restrict__ bo,
                                                 float* __restrict__ out) {
    extern __shared__ float sh[];
    float* aggS = sh;                           // [2][16][36]
    float* wovS = sh + 2 * KCH * AGG_STRIDE;    // [2][16][256]
    __shared__ float dots[N_TOK][32];
    __shared__ float invs[N_TOK][32];
    __shared__ float wgt[N_TOK][32];
    __shared__ float sg_s[C_DIM];
    __shared__ int s_tile;

    int tid = threadIdx.x;

    // roles (tile-invariant)
    int px2 = tid & 15;                 // B role: 2-pixel group
    int chb = tid >> 4;                 // B role: ch within 16-chunk
    int p4c = (tid & 7) * 4;            // GEMM px: 4 pixels
    int coo = (tid >> 3) * 8;           // GEMM: 8 co (4 f32x2 pairs)

    for (;;) {
        if (tid == 0) s_tile = atomicAdd(&g_tile_ctr, 1);
        __syncthreads();
        int t = s_tile;
        if (t >= N_TILES) break;
        int b = t >> 7;
        int p0 = (t & 127) * 32;

        {   // inline sg reduce
            float s = 0.f;
            #pragma unroll
            for (int i = 0; i < 16; ++i) s += g_sgp[i][b * C_DIM + tid];
            sg_s[tid] = s * g[tid] * rsqrtf((float)D_DIM);
        }

        const float* cb = c + (size_t)b * N_TOK * C_DIM * HW;

        #define STAGE_W(BUF, CH0) do {                                             \
            _Pragma("unroll")                                                      \
            for (int k = 0; k < 4; ++k) {                                          \
                int idx = tid + k * 256;                                           \
                int ch = idx >> 6, f = idx & 63;                                   \
                *(float4*)&wovS[((BUF) * KCH + ch) * C_DIM + f * 4] =              \
                    __ldg((const float4*)&g_wovgT[((CH0) + ch) * C_DIM] + f);      \
            }                                                                      \
        } while (0)

        // weight chunk 0 flies under phase A
        STAGE_W(0, 0);
        __syncthreads();   // sg_s ready

        // ---- Phase A: RMS + dot ----
        {
            int n = tid >> 5, p = tid & 31;
            const float* base = cb + (size_t)n * C_DIM * HW + p0 + p;
            float ss0 = 0.f, ss1 = 0.f, dt0 = 0.f, dt1 = 0.f;
            #pragma unroll 4
            for (int ch0 = 0; ch0 < C_DIM; ch0 += 8) {
                float4 sa = *(const float4*)&sg_s[ch0];
                float4 sb = *(const float4*)&sg_s[ch0 + 4];
                float v0 = __ldg(base + (size_t)(ch0 + 0) * HW);
                float v1 = __ldg(base + (size_t)(ch0 + 1) * HW);
                float v2 = __ldg(base + (size_t)(ch0 + 2) * HW);
                float v3 = __ldg(base + (size_t)(ch0 + 3) * HW);
                float v4 = __ldg(base + (size_t)(ch0 + 4) * HW);
                float v5 = __ldg(base + (size_t)(ch0 + 5) * HW);
                float v6 = __ldg(base + (size_t)(ch0 + 6) * HW);
                float v7 = __ldg(base + (size_t)(ch0 + 7) * HW);
                ss0 += v0 * v0 + v1 * v1 + v2 * v2 + v3 * v3;
                dt0 += v0 * sa.x + v1 * sa.y + v2 * sa.z + v3 * sa.w;
                ss1 += v4 * v4 + v5 * v5 + v6 * v6 + v7 * v7;
                dt1 += v4 * sb.x + v5 * sb.y + v6 * sb.z + v7 * sb.w;
            }
            float inv = rsqrtf((ss0 + ss1) * (1.0f / C_DIM) + EPS);
            dots[n][p] = (dt0 + dt1) * inv;
            invs[n][p] = inv;
        }
        __syncthreads();

        // ---- softmax ----
        {
            int n = tid >> 5, p = tid & 31;
            float m = dots[0][p];
            #pragma unroll
            for (int i = 1; i < N_TOK; ++i) m = fmaxf(m, dots[i][p]);
            float sum = 0.f;
            #pragma unroll
            for (int i = 0; i < N_TOK; ++i) sum += __expf(dots[i][p] - m);
            wgt[n][p] = __expf(dots[n][p] - m) / sum * invs[n][p];
        }
        __syncthreads();

        // B role: 16-ch chunk, thread = (ch, 2-px group); LDG.64 coalesced.
        #define B_CHUNK(BUF, CK) do {                                              \
            float2 a = make_float2(0.f, 0.f);                                      \
            int nch = (CK) * KCH + chb;                                            \
            _Pragma("unroll 4")                                                    \
            for (int n = 0; n < N_TOK; ++n) {                                      \
                float2 v = __ldg((const float2*)(cb +                              \
                              (size_t)(n * C_DIM + nch) * HW + p0 + px2 * 2));     \
                float2 w2 = *(const float2*)&wgt[n][px2 * 2];                      \
                a.x += w2.x * v.x; a.y += w2.y * v.y;                              \
            }                                                                      \
            *(float2*)&aggS[((BUF) * KCH + chb) * AGG_STRIDE + px2 * 2] = a;       \
        } while (0)

        B_CHUNK(0, 0);

        unsigned long long acc[4][4];       // [co-pair][px]
        #pragma unroll
        for (int i = 0; i < 4; ++i)
            #pragma unroll
            for (int j = 0; j < 4; ++j) acc[i][j] = 0ull;

        for (int ck = 0; ck < 16; ++ck) {
            __syncthreads();                // agg[ck&1] + wov[ck&1] ready
            if (ck < 15) {
                STAGE_W((ck + 1) & 1, (ck + 1) * KCH);
                B_CHUNK((ck + 1) & 1, ck + 1);
            }
            int cur = ck & 1;
            #pragma unroll
            for (int ch = 0; ch < KCH; ++ch) {
                float4 a4 = *(const float4*)&aggS[(cur * KCH + ch) * AGG_STRIDE + p4c];
                unsigned long long ad0, ad1, ad2, ad3;
                DUP2(ad0, a4.x); DUP2(ad1, a4.y); DUP2(ad2, a4.z); DUP2(ad3, a4.w);
                const ulonglong2* wp2 =
                    (const ulonglong2*)&wovS[(cur * KCH + ch) * C_DIM + coo];
                ulonglong2 w01 = wp2[0], w23 = wp2[1];
                FMA2(acc[0][0], w01.x, ad0, acc[0][0]); FMA2(acc[0][1], w01.x, ad1, acc[0][1]);
                FMA2(acc[0][2], w01.x, ad2, acc[0][2]); FMA2(acc[0][3], w01.x, ad3, acc[0][3]);
                FMA2(acc[1][0], w01.y, ad0, acc[1][0]); FMA2(acc[1][1], w01.y, ad1, acc[1][1]);
                FMA2(acc[1][2], w01.y, ad2, acc[1][2]); FMA2(acc[1][3], w01.y, ad3, acc[1][3]);
                FMA2(acc[2][0], w23.x, ad0, acc[2][0]); FMA2(acc[2][1], w23.x, ad1, acc[2][1]);
                FMA2(acc[2][2], w23.x, ad2, acc[2][2]); FMA2(acc[2][3], w23.x, ad3, acc[2][3]);
                FMA2(acc[3][0], w23.y, ad0, acc[3][0]); FMA2(acc[3][1], w23.y, ad1, acc[3][1]);
                FMA2(acc[3][2], w23.y, ad2, acc[3][2]); FMA2(acc[3][3], w23.y, ad3, acc[3][3]);
            }
        }
        #undef B_CHUNK
        #undef STAGE_W

        float* ob = out + ((size_t)b * C_DIM + coo) * HW + p0 + p4c;
        #pragma unroll
        for (int k = 0; k < 4; ++k) {
            float blo = __ldg(&bo[coo + 2 * k]);
            float bhi = __ldg(&bo[coo + 2 * k + 1]);
            unsigned lo[4], hi[4];
            #pragma unroll
            for (int j = 0; j < 4; ++j)
                asm("mov.b64 {%0, %1}, %2;" : "=r"(lo[j]), "=r"(hi[j]) : "l"(acc[k][j]));
            float4 rlo = make_float4(__uint_as_float(lo[0]) + blo, __uint_as_float(lo[1]) + blo,
                                     __uint_as_float(lo[2]) + blo, __uint_as_float(lo[3]) + blo);
            float4 rhi = make_float4(__uint_as_float(hi[0]) + bhi, __uint_as_float(hi[1]) + bhi,
                                     __uint_as_float(hi[2]) + bhi, __uint_as_float(hi[3]) + bhi);
            *(float4*)(ob + (size_t)(2 * k) * HW)     = rlo;
            *(float4*)(ob + (size_t)(2 * k + 1) * HW) = rhi;
        }
    }
}

extern "C" void kernel_launch(void* const* d_in, const int* in_sizes, int n_in,
                              void* d_out, int out_size) {
    const float* q   = (const float*)d_in[0];
    const float* c   = (const float*)d_in[1];
    const float* g   = (const float*)d_in[2];
    const float* Wq  = (const float*)d_in[3];
    const float* Wkv = (const float*)d_in[4];
    const float* Wo  = (const float*)d_in[5];
    const float* bo  = (const float*)d_in[6];
    float* out = (float*)d_out;

    cudaFuncSetAttribute(k_main, cudaFuncAttributeMaxDynamicSharedMemorySize, MAIN_SMEM);

    // 4 launches; ncu capture = absolute idx 3 = k_main.
    k_pro<<<320, 256>>>(q, Wq, Wkv, Wo);
    k_wovr<<<128, 256>>>(g, 0);        // also resets g_tile_ctr
    k_wovr<<<128, 256>>>(g, 32768);
    k_main<<<384, 256, MAIN_SMEM>>>(c, g, bo, out);   // persistent, ~2.6/SM
}

// round 17
// speedup vs baseline: 1.1798x; 1.1798x over previous
#include <cuda_runtime.h>
#include <cstdint>

#define C_DIM 256
#define N_TOK 8
#define D_DIM 512
#define HW    4096
#define B_SZ  4
#define EPS   1e-6f
#define N_TILES 512

// ---- persistent scratch ----
__device__ float g_sgp[16][B_SZ * C_DIM];
__device__ float g_wovp[16][C_DIM * C_DIM];   // partials (4MB), non-atomic
__device__ float g_wovgT[C_DIM * C_DIM];      // [ch][co]
__device__ int   g_tile_ctr;                  // dynamic tile counter

#define FMA2(d, a, b, c) \
    asm("fma.rn.f32x2 %0, %1, %2, %3;" : "=l"(d) : "l"(a), "l"(b), "l"(c))
#define DUP2(d, x) \
    asm("mov.b64 %0, {%1, %1};" : "=l"(d) : "r"(__float_as_uint(x)))

// ---------------------------------------------------------------------------
// L0 k_pro: merged prologue, 320 blocks.
//   [0,256):  wov partials, 16 co x 32 d per block
//   [256,320): sg partials
// ---------------------------------------------------------------------------
__global__ void k_pro(const float* __restrict__ q,  const float* __restrict__ Wq,
                      const float* __restrict__ Wkv, const float* __restrict__ Wo) {
    int blk = blockIdx.x, tid = threadIdx.x;
    if (blk < 256) {
        int co0 = (blk >> 4) * 16, kc = blk & 15;
        __shared__ float wo_s[16][32];
        #pragma unroll
        for (int k = 0; k < 2; ++k) {
            int idx = tid + k * 256;
            int r = idx >> 5, cc = idx & 31;
            wo_s[r][cc] = __ldg(&Wo[(co0 + r) * D_DIM + kc * 32 + cc]);
        }
        __syncthreads();
        const float* wv = Wkv + (size_t)(D_DIM + kc * 32) * C_DIM + tid;
        float a[16];
        #pragma unroll
        for (int r = 0; r < 16; ++r) a[r] = 0.f;
        #pragma unroll 4
        for (int d = 0; d < 32; ++d) {
            float v = __ldg(wv + (size_t)d * C_DIM);
            #pragma unroll
            for (int r = 0; r < 16; ++r) a[r] += wo_s[r][d] * v;
        }
        float* o = &g_wovp[kc][tid * C_DIM + co0];
        #pragma unroll
        for (int r = 0; r < 16; ++r) o[r] = a[r];
    } else {
        int s = blk - 256;
        int b = s >> 4, ck = s & 15;
        __shared__ float qs[C_DIM];
        __shared__ float qps[32];
        qs[tid] = q[b * C_DIM + tid];
        __syncthreads();
        {
            int dl = tid >> 3, sl = tid & 7;
            const float* wq = Wq + (size_t)(ck * 32 + dl) * C_DIM + sl * 32;
            float a = 0.f;
            #pragma unroll
            for (int k = 0; k < 32; ++k) a += __ldg(wq + k) * qs[sl * 32 + k];
            a += __shfl_xor_sync(0xffffffffu, a, 1);
            a += __shfl_xor_sync(0xffffffffu, a, 2);
            a += __shfl_xor_sync(0xffffffffu, a, 4);
            if (sl == 0) qps[dl] = a;
        }
        __syncthreads();
        float a = 0.f;
        const float* wk = Wkv + (size_t)(ck * 32) * C_DIM + tid;
        #pragma unroll
        for (int d = 0; d < 32; ++d) a += __ldg(wk + (size_t)d * C_DIM) * qps[d];
        g_sgp[ck][b * C_DIM + tid] = a;
    }
}

// ---------------------------------------------------------------------------
// L1 k_wovr (merged, 256 blocks): reduce partials; block 0 resets tile counter.
// ---------------------------------------------------------------------------
__global__ void k_wovr(const float* __restrict__ g) {
    if (blockIdx.x == 0 && threadIdx.x == 0) g_tile_ctr = 0;
    int idx = blockIdx.x * 256 + threadIdx.x;
    float s = 0.f;
    #pragma unroll
    for (int i = 0; i < 16; ++i) s += g_wovp[i][idx];
    g_wovgT[idx] = s * g[idx >> 8];
}

// ---------------------------------------------------------------------------
// L2 k_main: EXACT R15 form (measured 84.7us) — persistent + dynamic tiles,
// 32-ch chunks, double-buffered weights, 1 barrier/chunk, 2 blocks/SM.
// ---------------------------------------------------------------------------
#define AGG_STRIDE 36
#define MAIN_SMEM (2 * 32 * AGG_STRIDE * 4 + 2 * 32 * C_DIM * 4)   // 74752B
__global__ void __launch_bounds__(256, 2) k_main(const float* __restrict__ c,
                                                 const float* __restrict__ g,
                                                 const float* __restrict__ bo,
                                                 float* __restrict__ out) {
    extern __shared__ float sh[];
    float* aggS = sh;                          // [2][32][36]
    float* wovS = sh + 2 * 32 * AGG_STRIDE;    // [2][32][256]
    __shared__ float dots[N_TOK][32];
    __shared__ float invs[N_TOK][32];
    __shared__ float wgt[N_TOK][32];
    __shared__ float sg_s[C_DIM];
    __shared__ int s_tile;

    int tid = threadIdx.x;

    // roles (tile-invariant)
    int p4c = (tid & 7) * 4;            // 4 pixels (B role & GEMM px)
    int chi = tid >> 3;                 // B role: ch within chunk
    int coo = (tid >> 3) * 8;           // GEMM role: 8 co (4 f32x2 pairs)

    for (;;) {
        if (tid == 0) s_tile = atomicAdd(&g_tile_ctr, 1);
        __syncthreads();
        int t = s_tile;
        if (t >= N_TILES) break;
        int b = t >> 7;
        int p0 = (t & 127) * 32;

        {   // inline sg reduce
            float s = 0.f;
            #pragma unroll
            for (int i = 0; i < 16; ++i) s += g_sgp[i][b * C_DIM + tid];
            sg_s[tid] = s * g[tid] * rsqrtf((float)D_DIM);
        }

        const float* cb = c + (size_t)b * N_TOK * C_DIM * HW;

        #define STAGE_W(BUF, CH0) do {                                             \
            _Pragma("unroll")                                                      \
            for (int k = 0; k < 8; ++k) {                                          \
                int idx = tid + k * 256;                                           \
                int ch = idx >> 6, f = idx & 63;                                   \
                *(float4*)&wovS[((BUF) * 32 + ch) * C_DIM + f * 4] =               \
                    __ldg((const float4*)&g_wovgT[((CH0) + ch) * C_DIM] + f);      \
            }                                                                      \
        } while (0)

        // weight chunk 0 loads fly underneath phase A
        STAGE_W(0, 0);
        __syncthreads();   // sg_s ready

        // ---- Phase A: RMS + dot ----
        {
            int n = tid >> 5, p = tid & 31;
            const float* base = cb + (size_t)n * C_DIM * HW + p0 + p;
            float ss0 = 0.f, ss1 = 0.f, dt0 = 0.f, dt1 = 0.f;
            #pragma unroll 4
            for (int ch0 = 0; ch0 < C_DIM; ch0 += 8) {
                float4 sa = *(const float4*)&sg_s[ch0];
                float4 sb = *(const float4*)&sg_s[ch0 + 4];
                float v0 = __ldg(base + (size_t)(ch0 + 0) * HW);
                float v1 = __ldg(base + (size_t)(ch0 + 1) * HW);
                float v2 = __ldg(base + (size_t)(ch0 + 2) * HW);
                float v3 = __ldg(base + (size_t)(ch0 + 3) * HW);
                float v4 = __ldg(base + (size_t)(ch0 + 4) * HW);
                float v5 = __ldg(base + (size_t)(ch0 + 5) * HW);
                float v6 = __ldg(base + (size_t)(ch0 + 6) * HW);
                float v7 = __ldg(base + (size_t)(ch0 + 7) * HW);
                ss0 += v0 * v0 + v1 * v1 + v2 * v2 + v3 * v3;
                dt0 += v0 * sa.x + v1 * sa.y + v2 * sa.z + v3 * sa.w;
                ss1 += v4 * v4 + v5 * v5 + v6 * v6 + v7 * v7;
                dt1 += v4 * sb.x + v5 * sb.y + v6 * sb.z + v7 * sb.w;
            }
            float inv = rsqrtf((ss0 + ss1) * (1.0f / C_DIM) + EPS);
            dots[n][p] = (dt0 + dt1) * inv;
            invs[n][p] = inv;
        }
        __syncthreads();

        // ---- softmax ----
        {
            int n = tid >> 5, p = tid & 31;
            float m = dots[0][p];
            #pragma unroll
            for (int i = 1; i < N_TOK; ++i) m = fmaxf(m, dots[i][p]);
            float sum = 0.f;
            #pragma unroll
            for (int i = 0; i < N_TOK; ++i) sum += __expf(dots[i][p] - m);
            wgt[n][p] = __expf(dots[n][p] - m) / sum * invs[n][p];
        }
        __syncthreads();

        #define B_CHUNK(BUF, CK) do {                                              \
            float4 a = make_float4(0.f, 0.f, 0.f, 0.f);                            \
            int nch = (CK) * 32 + chi;                                             \
            _Pragma("unroll 4")                                                    \
            for (int n = 0; n < N_TOK; ++n) {                                      \
                float4 v = __ldg((const float4*)(cb +                              \
                              (size_t)(n * C_DIM + nch) * HW + p0 + p4c));         \
                float4 w4 = *(const float4*)&wgt[n][p4c];                          \
                a.x += w4.x * v.x; a.y += w4.y * v.y;                              \
                a.z += w4.z * v.z; a.w += w4.w * v.w;                              \
            }                                                                      \
            *(float4*)&aggS[((BUF) * 32 + chi) * AGG_STRIDE + p4c] = a;            \
        } while (0)

        B_CHUNK(0, 0);

        unsigned long long acc[4][4];       // [co-pair][px]
        #pragma unroll
        for (int i = 0; i < 4; ++i)
            #pragma unroll
            for (int j = 0; j < 4; ++j) acc[i][j] = 0ull;

        #pragma unroll
        for (int ck = 0; ck < 8; ++ck) {
            __syncthreads();                // agg[ck&1] + wov[ck&1] ready
            if (ck < 7) {
                STAGE_W((ck + 1) & 1, (ck + 1) * 32);
                B_CHUNK((ck + 1) & 1, ck + 1);
            }
            int cur = ck & 1;
            #pragma unroll
            for (int ch = 0; ch < 32; ++ch) {
                float4 a4 = *(const float4*)&aggS[(cur * 32 + ch) * AGG_STRIDE + p4c];
                unsigned long long ad0, ad1, ad2, ad3;
                DUP2(ad0, a4.x); DUP2(ad1, a4.y); DUP2(ad2, a4.z); DUP2(ad3, a4.w);
                const ulonglong2* wp2 =
                    (const ulonglong2*)&wovS[(cur * 32 + ch) * C_DIM + coo];
                ulonglong2 w01 = wp2[0], w23 = wp2[1];
                FMA2(acc[0][0], w01.x, ad0, acc[0][0]); FMA2(acc[0][1], w01.x, ad1, acc[0][1]);
                FMA2(acc[0][2], w01.x, ad2, acc[0][2]); FMA2(acc[0][3], w01.x, ad3, acc[0][3]);
                FMA2(acc[1][0], w01.y, ad0, acc[1][0]); FMA2(acc[1][1], w01.y, ad1, acc[1][1]);
                FMA2(acc[1][2], w01.y, ad2, acc[1][2]); FMA2(acc[1][3], w01.y, ad3, acc[1][3]);
                FMA2(acc[2][0], w23.x, ad0, acc[2][0]); FMA2(acc[2][1], w23.x, ad1, acc[2][1]);
                FMA2(acc[2][2], w23.x, ad2, acc[2][2]); FMA2(acc[2][3], w23.x, ad3, acc[2][3]);
                FMA2(acc[3][0], w23.y, ad0, acc[3][0]); FMA2(acc[3][1], w23.y, ad1, acc[3][1]);
                FMA2(acc[3][2], w23.y, ad2, acc[3][2]); FMA2(acc[3][3], w23.y, ad3, acc[3][3]);
            }
        }
        #undef B_CHUNK
        #undef STAGE_W

        float* ob = out + ((size_t)b * C_DIM + coo) * HW + p0 + p4c;
        #pragma unroll
        for (int k = 0; k < 4; ++k) {
            float blo = __ldg(&bo[coo + 2 * k]);
            float bhi = __ldg(&bo[coo + 2 * k + 1]);
            unsigned lo[4], hi[4];
            #pragma unroll
            for (int j = 0; j < 4; ++j)
                asm("mov.b64 {%0, %1}, %2;" : "=r"(lo[j]), "=r"(hi[j]) : "l"(acc[k][j]));
            float4 rlo = make_float4(__uint_as_float(lo[0]) + blo, __uint_as_float(lo[1]) + blo,
                                     __uint_as_float(lo[2]) + blo, __uint_as_float(lo[3]) + blo);
            float4 rhi = make_float4(__uint_as_float(hi[0]) + bhi, __uint_as_float(hi[1]) + bhi,
                                     __uint_as_float(hi[2]) + bhi, __uint_as_float(hi[3]) + bhi);
            *(float4*)(ob + (size_t)(2 * k) * HW)     = rlo;
            *(float4*)(ob + (size_t)(2 * k + 1) * HW) = rhi;
        }
    }
}

extern "C" void kernel_launch(void* const* d_in, const int* in_sizes, int n_in,
                              void* d_out, int out_size) {
    const float* q   = (const float*)d_in[0];
    const float* c   = (const float*)d_in[1];
    const float* g   = (const float*)d_in[2];
    const float* Wq  = (const float*)d_in[3];
    const float* Wkv = (const float*)d_in[4];
    const float* Wo  = (const float*)d_in[5];
    const float* bo  = (const float*)d_in[6];
    float* out = (float*)d_out;

    cudaFuncSetAttribute(k_main, cudaFuncAttributeMaxDynamicSharedMemorySize, MAIN_SMEM);

    // 3 launches; ncu capture (abs idx 3) = k_pro — prologue is the next target.
    k_pro<<<320, 256>>>(q, Wq, Wkv, Wo);
    k_wovr<<<256, 256>>>(g);           // merged; also resets g_tile_ctr
    k_main<<<304, 256, MAIN_SMEM>>>(c, g, bo, out);   // persistent, 2/SM
}